// round 2
// baseline (speedup 1.0000x reference)
#include <cuda_runtime.h>
#include <cuda_fp16.h>
#include <cstdint>

#define HW_ 262144            // 512*512
#define NPIX 1048576          // 4*512*512
#define TILE 128
#define GRID 8192

// Fragment-linear fp16 weight images for mma.sync m16n8k16 B operand.
// Layout: [layer][kb(16)][n8pair(16)][lane(32)][8 halfs]
__device__ __align__(16) __half g_bf[3][65536];

// ---------------- prep: fp32 W -> fp16 fragment-linear ----------------
__global__ void prep_kernel(const float* __restrict__ W1, const float* __restrict__ W2,
                            const float* __restrict__ W3) {
  int t = blockIdx.x * blockDim.x + threadIdx.x;   // 3*65536 threads
  int l = t >> 16, e = t & 65535;
  int k = e >> 8, n = e & 255;
  const float* W = (l == 0) ? W1 : (l == 1 ? W2 : W3);
  int kb = k >> 4, kr = k & 15;
  int n8 = n >> 3, g = n & 7;
  int tg = (kr >> 1) & 3;
  int lane = g * 4 + tg;
  int breg = kr >> 3, hs = kr & 1;
  int halfidx = (n8 & 1) * 4 + breg * 2 + hs;
  int dst = ((kb * 16 + (n8 >> 1)) * 32 + lane) * 8 + halfidx;
  g_bf[l][dst] = __float2half_rn(W[k * 256 + n]);
}

// ---------------- helpers ----------------
__device__ __forceinline__ uint32_t smem_u32(const void* p) {
  uint32_t a;
  asm("{ .reg .u64 t; cvta.to.shared.u64 t, %1; cvt.u32.u64 %0, t; }" : "=r"(a) : "l"(p));
  return a;
}
__device__ __forceinline__ void cp16(uint32_t dst, const void* src) {
  asm volatile("cp.async.cg.shared.global [%0], [%1], 16;" :: "r"(dst), "l"(src) : "memory");
}
__device__ __forceinline__ uint32_t packh2(float lo, float hi) {
  uint32_t r;
  asm("cvt.rn.f16x2.f32 %0, %1, %2;" : "=r"(r) : "f"(hi), "f"(lo));  // a->hi, b->lo
  return r;
}
// accurate tanh: tanh(x) = 1 - 2/(exp(2x)+1), 2 MUFU ops
__device__ __forceinline__ float tanh_fast(float x) {
  float e, r;
  asm("ex2.approx.f32 %0, %1;" : "=f"(e) : "f"(x * 2.885390081777927f));
  asm("rcp.approx.f32 %0, %1;" : "=f"(r) : "f"(e + 1.0f));
  return fmaf(-2.0f, r, 1.0f);
}
__device__ __forceinline__ void mma16816(float* c, const uint4& a, uint32_t b0, uint32_t b1) {
  asm volatile("mma.sync.aligned.m16n8k16.row.col.f32.f16.f16.f32 "
               "{%0,%1,%2,%3}, {%4,%5,%6,%7}, {%8,%9}, {%0,%1,%2,%3};"
               : "+f"(c[0]), "+f"(c[1]), "+f"(c[2]), "+f"(c[3])
               : "r"(a.x), "r"(a.y), "r"(a.z), "r"(a.w), "r"(b0), "r"(b1));
}

// ---------------- main kernel ----------------
// SMEM: A 64KB fragment-linear fp16 acts | B 128KB weights | params ~10KB
#define A_OFF 0
#define B_OFF 65536
#define SC0_OFF 196608
#define SW0_OFF 197632
#define SB_OFF  200704
#define SW4_OFF 203776
#define SB4_OFF 206848
#define SMEM_TOTAL 206976

__global__ void __launch_bounds__(256, 1) cnilut_main(
    const float* __restrict__ x, const float* __restrict__ style,
    const float* __restrict__ W0, const float* __restrict__ b0,
    const float* __restrict__ b1, const float* __restrict__ b2,
    const float* __restrict__ b3, const float* __restrict__ W4,
    const float* __restrict__ b4, float* __restrict__ out) {
  extern __shared__ char smem[];
  uint4* sA = (uint4*)(smem + A_OFF);    // [(m_blk*16+kb)*32+lane]
  uint4* sB = (uint4*)(smem + B_OFF);    // [(kb*16+pair)*32+lane]
  float* sc0 = (float*)(smem + SC0_OFF);
  float* sw0 = (float*)(smem + SW0_OFF);
  float* sb  = (float*)(smem + SB_OFF);
  float* sw4 = (float*)(smem + SW4_OFF);
  float* sb4 = (float*)(smem + SB4_OFF);

  int tid = threadIdx.x, wid = tid >> 5, lane = tid & 31;
  int g = lane >> 2, tg = lane & 3;

  // prefetch layer-1 weights into SMEM (overlaps layer0 compute)
  uint32_t bbase = smem_u32(smem + B_OFF);
  {
    const char* src = (const char*)g_bf[0];
    #pragma unroll
    for (int i = 0; i < 32; i++)
      cp16(bbase + (uint32_t)(tid + i * 256) * 16, src + (size_t)(tid + i * 256) * 16);
    asm volatile("cp.async.commit_group;" ::: "memory");
  }

  // per-CTA params
  {
    float s0 = style[0], s1 = style[1], s2 = style[2];
    sw0[tid]       = W0[tid];
    sw0[256 + tid] = W0[256 + tid];
    sw0[512 + tid] = W0[512 + tid];
    sc0[tid] = b0[tid] + s0 * W0[768 + tid] + s1 * W0[1024 + tid] + s2 * W0[1280 + tid];
    sb[tid]       = b1[tid];
    sb[256 + tid] = b2[tid];
    sb[512 + tid] = b3[tid];
    sw4[tid]       = W4[tid];
    sw4[256 + tid] = W4[256 + tid];
    sw4[512 + tid] = W4[512 + tid];
    if (tid < 3) sb4[tid] = b4[tid];
  }
  __syncthreads();

  // this thread's two pixels (layer0 + final): rows g and g+8 of m-block `wid`
  int p0 = blockIdx.x * TILE + wid * 16 + g;
  int img = p0 >> 18, hw = p0 & (HW_ - 1);
  const float* xb = x + (size_t)img * 3 * HW_ + hw;
  float xv[2][3];
  #pragma unroll
  for (int c = 0; c < 3; c++) { xv[0][c] = xb[(size_t)c * HW_]; xv[1][c] = xb[(size_t)c * HW_ + 8]; }

  // ---- layer 0: h = relu(x.W0 + c0); write A fragments ----
  #pragma unroll 4
  for (int kb = 0; kb < 16; kb++) {
    int k0 = kb * 16 + tg * 2;
    uint32_t a[4];
    #pragma unroll
    for (int half8 = 0; half8 < 2; half8++) {       // k0 / k0+8
      int u = k0 + half8 * 8;
      float w0a = sw0[u],       w0b = sw0[u + 1];
      float w1a = sw0[256 + u], w1b = sw0[257 + u];
      float w2a = sw0[512 + u], w2b = sw0[513 + u];
      float ca = sc0[u], cb = sc0[u + 1];
      #pragma unroll
      for (int pi = 0; pi < 2; pi++) {
        float ha = fmaxf(ca + xv[pi][0] * w0a + xv[pi][1] * w1a + xv[pi][2] * w2a, 0.f);
        float hb = fmaxf(cb + xv[pi][0] * w0b + xv[pi][1] * w1b + xv[pi][2] * w2b, 0.f);
        a[half8 * 2 + pi] = packh2(ha, hb);
      }
    }
    sA[(wid * 16 + kb) * 32 + lane] = make_uint4(a[0], a[1], a[2], a[3]);
  }
  asm volatile("cp.async.wait_group 0;" ::: "memory");
  __syncthreads();

  // ---- 3 hidden layers: [128x256] @ [256x256], warp tile 64x64 ----
  int wm = wid >> 2, wn = wid & 3;
  float acc[4][8][4];

  #pragma unroll 1
  for (int l = 0; l < 3; l++) {
    #pragma unroll
    for (int i = 0; i < 4; i++)
      #pragma unroll
      for (int j = 0; j < 8; j++)
        #pragma unroll
        for (int r = 0; r < 4; r++) acc[i][j][r] = 0.f;

    #pragma unroll 2
    for (int kb = 0; kb < 16; kb++) {
      uint4 af[4], bf[4];
      #pragma unroll
      for (int i = 0; i < 4; i++) af[i] = sA[((wm * 4 + i) * 16 + kb) * 32 + lane];
      #pragma unroll
      for (int j = 0; j < 4; j++) bf[j] = sB[(kb * 16 + wn * 4 + j) * 32 + lane];
      #pragma unroll
      for (int i = 0; i < 4; i++)
        #pragma unroll
        for (int j = 0; j < 4; j++) {
          mma16816(acc[i][2 * j],     af[i], bf[j].x, bf[j].y);
          mma16816(acc[i][2 * j + 1], af[i], bf[j].z, bf[j].w);
        }
    }
    __syncthreads();   // all A/B reads for this layer done

    // prefetch next layer weights (overlaps epilogue)
    if (l < 2) {
      const char* src = (const char*)g_bf[l + 1];
      #pragma unroll
      for (int i = 0; i < 32; i++)
        cp16(bbase + (uint32_t)(tid + i * 256) * 16, src + (size_t)(tid + i * 256) * 16);
      asm volatile("cp.async.commit_group;" ::: "memory");
    }

    // epilogue: bias + tanh, pack into A fragments (register-local remap)
    const float* bias = sb + l * 256;
    #pragma unroll
    for (int i = 0; i < 4; i++) {
      #pragma unroll
      for (int jj = 0; jj < 4; jj++) {
        int c = wn * 64 + jj * 16 + tg * 2;
        float b0v = bias[c], b1v = bias[c + 1], b8v = bias[c + 8], b9v = bias[c + 9];
        float* e = acc[i][2 * jj];
        float* o = acc[i][2 * jj + 1];
        uint32_t a0 = packh2(tanh_fast(e[0] + b0v), tanh_fast(e[1] + b1v));
        uint32_t a1 = packh2(tanh_fast(e[2] + b0v), tanh_fast(e[3] + b1v));
        uint32_t a2 = packh2(tanh_fast(o[0] + b8v), tanh_fast(o[1] + b9v));
        uint32_t a3 = packh2(tanh_fast(o[2] + b8v), tanh_fast(o[3] + b9v));
        sA[((wm * 4 + i) * 16 + (wn * 4 + jj)) * 32 + lane] = make_uint4(a0, a1, a2, a3);
      }
    }
    if (l < 2) asm volatile("cp.async.wait_group 0;" ::: "memory");
    __syncthreads();   // A stores + B copies visible
  }

  // ---- final: res = z @ W4 + b4; out = clip(x + res) ----
  float r0[3] = {0.f, 0.f, 0.f}, r1[3] = {0.f, 0.f, 0.f};
  #pragma unroll 4
  for (int kb = 0; kb < 16; kb++) {
    uint4 a = sA[(wid * 16 + kb) * 32 + lane];
    int k0 = kb * 16 + tg * 2;
    uint32_t regs[4] = {a.x, a.y, a.z, a.w};
    #pragma unroll
    for (int half8 = 0; half8 < 2; half8++) {
      int u = k0 + half8 * 8;
      float w_a[3], w_b[3];
      #pragma unroll
      for (int c = 0; c < 3; c++) { w_a[c] = sw4[u * 3 + c]; w_b[c] = sw4[(u + 1) * 3 + c]; }
      #pragma unroll
      for (int pi = 0; pi < 2; pi++) {
        __half2 h = *(__half2*)&regs[half8 * 2 + pi];
        float za = __half2float(__low2half(h)), zb = __half2float(__high2half(h));
        float* r = pi ? r1 : r0;
        #pragma unroll
        for (int c = 0; c < 3; c++) r[c] += za * w_a[c] + zb * w_b[c];
      }
    }
  }
  #pragma unroll
  for (int c = 0; c < 3; c++) {
    r0[c] += __shfl_xor_sync(0xFFFFFFFF, r0[c], 1);
    r0[c] += __shfl_xor_sync(0xFFFFFFFF, r0[c], 2);
    r1[c] += __shfl_xor_sync(0xFFFFFFFF, r1[c], 1);
    r1[c] += __shfl_xor_sync(0xFFFFFFFF, r1[c], 2);
  }
  if (tg < 3) {
    float o0 = fminf(fmaxf(xv[0][tg] + r0[tg] + sb4[tg], 0.f), 1.f);
    float o1 = fminf(fmaxf(xv[1][tg] + r1[tg] + sb4[tg], 0.f), 1.f);
    float* ob = out + (size_t)img * 3 * HW_ + (size_t)tg * HW_ + hw;
    ob[0] = o0; ob[8] = o1;
  }
}

extern "C" void kernel_launch(void* const* d_in, const int* in_sizes, int n_in,
                              void* d_out, int out_size) {
  const float* x     = (const float*)d_in[0];
  const float* style = (const float*)d_in[1];
  const float* W0    = (const float*)d_in[2];
  const float* b0    = (const float*)d_in[3];
  const float* W1    = (const float*)d_in[4];
  const float* b1    = (const float*)d_in[5];
  const float* W2    = (const float*)d_in[6];
  const float* b2    = (const float*)d_in[7];
  const float* W3    = (const float*)d_in[8];
  const float* b3    = (const float*)d_in[9];
  const float* W4    = (const float*)d_in[10];
  const float* b4    = (const float*)d_in[11];
  float* out = (float*)d_out;

  prep_kernel<<<768, 256>>>(W1, W2, W3);

  cudaFuncSetAttribute(cnilut_main, cudaFuncAttributeMaxDynamicSharedMemorySize, SMEM_TOTAL);
  cnilut_main<<<GRID, 256, SMEM_TOTAL>>>(x, style, W0, b0, b1, b2, b3, W4, b4, out);
}

// round 3
// speedup vs baseline: 1.4437x; 1.4437x over previous
#include <cuda_runtime.h>
#include <cuda_fp16.h>
#include <cstdint>

#define HW_ 262144            // 512*512
#define TILE 64
#define GRID 16384

// Fragment-linear fp16 weight images for mma.sync m16n8k16 B operand.
// Layout: [layer][kb(16)][n8pair(16)][lane(32)][8 halfs]
__device__ __align__(16) __half g_bf[3][65536];

// ---------------- prep: fp32 W -> fp16 fragment-linear ----------------
__global__ void prep_kernel(const float* __restrict__ W1, const float* __restrict__ W2,
                            const float* __restrict__ W3) {
  int t = blockIdx.x * blockDim.x + threadIdx.x;   // 3*65536 threads
  int l = t >> 16, e = t & 65535;
  int k = e >> 8, n = e & 255;
  const float* W = (l == 0) ? W1 : (l == 1 ? W2 : W3);
  int kb = k >> 4, kr = k & 15;
  int n8 = n >> 3, g = n & 7;
  int tg = (kr >> 1) & 3;
  int lane = g * 4 + tg;
  int breg = kr >> 3, hs = kr & 1;
  int halfidx = (n8 & 1) * 4 + breg * 2 + hs;
  int dst = ((kb * 16 + (n8 >> 1)) * 32 + lane) * 8 + halfidx;
  g_bf[l][dst] = __float2half_rn(W[k * 256 + n]);
}

// ---------------- helpers ----------------
__device__ __forceinline__ uint32_t packh2(float lo, float hi) {
  uint32_t r;
  asm("cvt.rn.f16x2.f32 %0, %1, %2;" : "=f"(*(float*)&r) : "f"(hi), "f"(lo));
  return r;
}
__device__ __forceinline__ float tanh_fast(float x) {
  float r;
  asm("tanh.approx.f32 %0, %1;" : "=f"(r) : "f"(x));
  return r;
}
__device__ __forceinline__ void mma16816(float* c, const uint4& a, uint32_t b0, uint32_t b1) {
  asm volatile("mma.sync.aligned.m16n8k16.row.col.f32.f16.f16.f32 "
               "{%0,%1,%2,%3}, {%4,%5,%6,%7}, {%8,%9}, {%0,%1,%2,%3};"
               : "+f"(c[0]), "+f"(c[1]), "+f"(c[2]), "+f"(c[3])
               : "r"(a.x), "r"(a.y), "r"(a.z), "r"(a.w), "r"(b0), "r"(b1));
}

// ---------------- main kernel: 128 threads (4 warps), 64 pixels, 2 CTAs/SM ----
__global__ void __launch_bounds__(128, 2) cnilut_main(
    const float* __restrict__ x, const float* __restrict__ style,
    const float* __restrict__ W0, const float* __restrict__ b0,
    const float* __restrict__ b1, const float* __restrict__ b2,
    const float* __restrict__ b3, const float* __restrict__ W4,
    const float* __restrict__ b4, float* __restrict__ out) {
  __shared__ uint4 sA[2048];          // 32KB: [(mblk*16+kb)*32+lane]
  __shared__ float sc0[256];
  __shared__ float sw0[768];
  __shared__ float sb[768];
  __shared__ float sw4[768];
  __shared__ float sb4[3];

  int tid = threadIdx.x, wid = tid >> 5, lane = tid & 31;
  int g = lane >> 2, tg = lane & 3;

  // per-CTA params
  {
    float s0 = style[0], s1 = style[1], s2 = style[2];
    #pragma unroll
    for (int i = 0; i < 6; i++) {
      int u = tid + i * 128;
      sw0[u] = W0[u];
      sb[u]  = (u < 256) ? b1[u] : (u < 512 ? b2[u - 256] : b3[u - 512]);
      sw4[u] = W4[u];
    }
    #pragma unroll
    for (int i = 0; i < 2; i++) {
      int u = tid + i * 128;
      sc0[u] = b0[u] + s0 * W0[768 + u] + s1 * W0[1024 + u] + s2 * W0[1280 + u];
    }
    if (tid < 3) sb4[tid] = b4[tid];
  }

  // this thread's two pixels: rows g and g+8 of m-block `wid`
  int p0 = blockIdx.x * TILE + wid * 16 + g;
  int img = p0 >> 18, hw = p0 & (HW_ - 1);
  const float* xb = x + (size_t)img * 3 * HW_ + hw;
  float xv[2][3];
  #pragma unroll
  for (int c = 0; c < 3; c++) { xv[0][c] = xb[(size_t)c * HW_]; xv[1][c] = xb[(size_t)c * HW_ + 8]; }
  __syncthreads();

  // ---- layer 0: h = relu(x.W0 + c0); warp wid writes m-block wid ----
  #pragma unroll 4
  for (int kb = 0; kb < 16; kb++) {
    int k0 = kb * 16 + tg * 2;
    uint32_t a[4];
    #pragma unroll
    for (int half8 = 0; half8 < 2; half8++) {
      int u = k0 + half8 * 8;
      float w0a = sw0[u],       w0b = sw0[u + 1];
      float w1a = sw0[256 + u], w1b = sw0[257 + u];
      float w2a = sw0[512 + u], w2b = sw0[513 + u];
      float ca = sc0[u], cb = sc0[u + 1];
      #pragma unroll
      for (int pi = 0; pi < 2; pi++) {
        float ha = fmaxf(ca + xv[pi][0] * w0a + xv[pi][1] * w1a + xv[pi][2] * w2a, 0.f);
        float hb = fmaxf(cb + xv[pi][0] * w0b + xv[pi][1] * w1b + xv[pi][2] * w2b, 0.f);
        a[half8 * 2 + pi] = packh2(ha, hb);
      }
    }
    sA[(wid * 16 + kb) * 32 + lane] = make_uint4(a[0], a[1], a[2], a[3]);
  }
  __syncthreads();

  // ---- 3 hidden layers: warp tile 64x64 (wm=0, wn=wid); B via LDG from L2/L1 ----
  float acc[4][8][4];

  #pragma unroll 1
  for (int l = 0; l < 3; l++) {
    #pragma unroll
    for (int i = 0; i < 4; i++)
      #pragma unroll
      for (int j = 0; j < 8; j++)
        #pragma unroll
        for (int r = 0; r < 4; r++) acc[i][j][r] = 0.f;

    const uint4* gB = (const uint4*)g_bf[l];
    uint4 bf[3][4];
    #pragma unroll
    for (int j = 0; j < 4; j++) {
      bf[0][j] = __ldg(gB + (0 * 16 + wid * 4 + j) * 32 + lane);
      bf[1][j] = __ldg(gB + (1 * 16 + wid * 4 + j) * 32 + lane);
    }

    #pragma unroll
    for (int kb = 0; kb < 16; kb++) {
      int cur = kb % 3;
      if (kb < 14) {
        int nxt = (kb + 2) % 3;
        #pragma unroll
        for (int j = 0; j < 4; j++)
          bf[nxt][j] = __ldg(gB + ((kb + 2) * 16 + wid * 4 + j) * 32 + lane);
      }
      uint4 af[4];
      #pragma unroll
      for (int i = 0; i < 4; i++) af[i] = sA[(i * 16 + kb) * 32 + lane];
      #pragma unroll
      for (int i = 0; i < 4; i++)
        #pragma unroll
        for (int j = 0; j < 4; j++) {
          mma16816(acc[i][2 * j],     af[i], bf[cur][j].x, bf[cur][j].y);
          mma16816(acc[i][2 * j + 1], af[i], bf[cur][j].z, bf[cur][j].w);
        }
    }
    __syncthreads();   // all A reads for this layer done

    // epilogue: bias + tanh, pack into A fragments (register-local remap)
    const float* bias = sb + l * 256;
    #pragma unroll
    for (int jj = 0; jj < 4; jj++) {
      int c = wid * 64 + jj * 16 + tg * 2;
      float b0v = bias[c], b1v = bias[c + 1], b8v = bias[c + 8], b9v = bias[c + 9];
      #pragma unroll
      for (int i = 0; i < 4; i++) {
        float* e = acc[i][2 * jj];
        float* o = acc[i][2 * jj + 1];
        uint32_t a0 = packh2(tanh_fast(e[0] + b0v), tanh_fast(e[1] + b1v));
        uint32_t a1 = packh2(tanh_fast(e[2] + b0v), tanh_fast(e[3] + b1v));
        uint32_t a2 = packh2(tanh_fast(o[0] + b8v), tanh_fast(o[1] + b9v));
        uint32_t a3 = packh2(tanh_fast(o[2] + b8v), tanh_fast(o[3] + b9v));
        sA[(i * 16 + (wid * 4 + jj)) * 32 + lane] = make_uint4(a0, a1, a2, a3);
      }
    }
    __syncthreads();
  }

  // ---- final: res = z @ W4 + b4; out = clip(x + res) ----
  float r0[3] = {0.f, 0.f, 0.f}, r1[3] = {0.f, 0.f, 0.f};
  #pragma unroll 4
  for (int kb = 0; kb < 16; kb++) {
    uint4 a = sA[(wid * 16 + kb) * 32 + lane];
    int k0 = kb * 16 + tg * 2;
    uint32_t regs[4] = {a.x, a.y, a.z, a.w};
    #pragma unroll
    for (int half8 = 0; half8 < 2; half8++) {
      int u = k0 + half8 * 8;
      float w_a[3], w_b[3];
      #pragma unroll
      for (int c = 0; c < 3; c++) { w_a[c] = sw4[u * 3 + c]; w_b[c] = sw4[(u + 1) * 3 + c]; }
      #pragma unroll
      for (int pi = 0; pi < 2; pi++) {
        __half2 h = *(__half2*)&regs[half8 * 2 + pi];
        float za = __half2float(__low2half(h)), zb = __half2float(__high2half(h));
        float* r = pi ? r1 : r0;
        #pragma unroll
        for (int c = 0; c < 3; c++) r[c] += za * w_a[c] + zb * w_b[c];
      }
    }
  }
  #pragma unroll
  for (int c = 0; c < 3; c++) {
    r0[c] += __shfl_xor_sync(0xFFFFFFFF, r0[c], 1);
    r0[c] += __shfl_xor_sync(0xFFFFFFFF, r0[c], 2);
    r1[c] += __shfl_xor_sync(0xFFFFFFFF, r1[c], 1);
    r1[c] += __shfl_xor_sync(0xFFFFFFFF, r1[c], 2);
  }
  if (tg < 3) {
    float o0 = fminf(fmaxf(xv[0][tg] + r0[tg] + sb4[tg], 0.f), 1.f);
    float o1 = fminf(fmaxf(xv[1][tg] + r1[tg] + sb4[tg], 0.f), 1.f);
    float* ob = out + (size_t)img * 3 * HW_ + (size_t)tg * HW_ + hw;
    ob[0] = o0; ob[8] = o1;
  }
}

extern "C" void kernel_launch(void* const* d_in, const int* in_sizes, int n_in,
                              void* d_out, int out_size) {
  const float* x     = (const float*)d_in[0];
  const float* style = (const float*)d_in[1];
  const float* W0    = (const float*)d_in[2];
  const float* b0    = (const float*)d_in[3];
  const float* W1    = (const float*)d_in[4];
  const float* b1    = (const float*)d_in[5];
  const float* W2    = (const float*)d_in[6];
  const float* b2    = (const float*)d_in[7];
  const float* W3    = (const float*)d_in[8];
  const float* b3    = (const float*)d_in[9];
  const float* W4    = (const float*)d_in[10];
  const float* b4    = (const float*)d_in[11];
  float* out = (float*)d_out;

  prep_kernel<<<768, 256>>>(W1, W2, W3);
  cnilut_main<<<GRID, 128>>>(x, style, W0, b0, b1, b2, b3, W4, b4, out);
}

// round 4
// speedup vs baseline: 1.5307x; 1.0603x over previous
#include <cuda_runtime.h>
#include <cuda_fp16.h>
#include <cstdint>

#define HW_ 262144            // 512*512
#define TILE 64
#define GRID 16384

// Fragment-linear fp16 weight images for mma.sync m16n8k16 B operand.
// Layout: [layer][kb(16)][n8pair(16)][lane(32)][8 halfs]
__device__ __align__(16) __half g_bf[3][65536];

// ---------------- prep: fp32 W -> fp16 fragment-linear ----------------
__global__ void prep_kernel(const float* __restrict__ W1, const float* __restrict__ W2,
                            const float* __restrict__ W3) {
  int t = blockIdx.x * blockDim.x + threadIdx.x;   // 3*65536 threads
  int l = t >> 16, e = t & 65535;
  int k = e >> 8, n = e & 255;
  const float* W = (l == 0) ? W1 : (l == 1 ? W2 : W3);
  int kb = k >> 4, kr = k & 15;
  int n8 = n >> 3, g = n & 7;
  int tg = (kr >> 1) & 3;
  int lane = g * 4 + tg;
  int breg = kr >> 3, hs = kr & 1;
  int halfidx = (n8 & 1) * 4 + breg * 2 + hs;
  int dst = ((kb * 16 + (n8 >> 1)) * 32 + lane) * 8 + halfidx;
  g_bf[l][dst] = __float2half_rn(W[k * 256 + n]);
}

// ---------------- helpers ----------------
__device__ __forceinline__ uint32_t packh2(float lo, float hi) {
  uint32_t r;
  asm("cvt.rn.f16x2.f32 %0, %1, %2;" : "=f"(*(float*)&r) : "f"(hi), "f"(lo));
  return r;
}
__device__ __forceinline__ uint32_t tanh2(uint32_t p) {
  uint32_t r;
  asm("tanh.approx.f16x2 %0, %1;" : "=r"(r) : "r"(p));
  return r;
}
__device__ __forceinline__ void mma16816(float* c, const uint4& a, uint32_t b0, uint32_t b1) {
  asm volatile("mma.sync.aligned.m16n8k16.row.col.f32.f16.f16.f32 "
               "{%0,%1,%2,%3}, {%4,%5,%6,%7}, {%8,%9}, {%0,%1,%2,%3};"
               : "+f"(c[0]), "+f"(c[1]), "+f"(c[2]), "+f"(c[3])
               : "r"(a.x), "r"(a.y), "r"(a.z), "r"(a.w), "r"(b0), "r"(b1));
}

// ---------------- SMEM layout (dynamic, 75776 B/CTA) ----------------
// [0:65536)       sA double-buffered: 2 x 2048 uint4
// [65536:66560)   sc0 (256 f)
// [66560:69632)   sw0 (768 f)
// [69632:72704)   sb  (768 f)
// [72704:75776)   sw4 (768 f)  (+ sb4 3 f packed at end of sw4 pad)
#define SMEM_TOTAL 75792

__global__ void __launch_bounds__(128, 2) cnilut_main(
    const float* __restrict__ x, const float* __restrict__ style,
    const float* __restrict__ W0, const float* __restrict__ b0,
    const float* __restrict__ b1, const float* __restrict__ b2,
    const float* __restrict__ b3, const float* __restrict__ W4,
    const float* __restrict__ b4, float* __restrict__ out) {
  extern __shared__ char smem[];
  uint4* sA  = (uint4*)smem;                  // 2 buffers of 2048
  float* sc0 = (float*)(smem + 65536);
  float* sw0 = (float*)(smem + 66560);
  float* sb  = (float*)(smem + 69632);
  float* sw4 = (float*)(smem + 72704);
  float* sb4 = (float*)(smem + 75776);

  int tid = threadIdx.x, wid = tid >> 5, lane = tid & 31;
  int g = lane >> 2, tg = lane & 3;

  // per-CTA params
  {
    float s0 = style[0], s1 = style[1], s2 = style[2];
    #pragma unroll
    for (int i = 0; i < 6; i++) {
      int u = tid + i * 128;
      sw0[u] = W0[u];
      sb[u]  = (u < 256) ? b1[u] : (u < 512 ? b2[u - 256] : b3[u - 512]);
      sw4[u] = W4[u];
    }
    #pragma unroll
    for (int i = 0; i < 2; i++) {
      int u = tid + i * 128;
      sc0[u] = b0[u] + s0 * W0[768 + u] + s1 * W0[1024 + u] + s2 * W0[1280 + u];
    }
    if (tid < 3) sb4[tid] = b4[tid];
  }

  // this thread's two pixels: rows g and g+8 of m-block `wid`
  int p0 = blockIdx.x * TILE + wid * 16 + g;
  int img = p0 >> 18, hw = p0 & (HW_ - 1);
  const float* xb = x + (size_t)img * 3 * HW_ + hw;
  float xv[2][3];
  #pragma unroll
  for (int c = 0; c < 3; c++) { xv[0][c] = xb[(size_t)c * HW_]; xv[1][c] = xb[(size_t)c * HW_ + 8]; }
  __syncthreads();

  // ---- layer 0: h = relu(x.W0 + c0) -> sA buffer 0 ----
  #pragma unroll 4
  for (int kb = 0; kb < 16; kb++) {
    int k0 = kb * 16 + tg * 2;
    uint32_t a[4];
    #pragma unroll
    for (int half8 = 0; half8 < 2; half8++) {
      int u = k0 + half8 * 8;
      float w0a = sw0[u],       w0b = sw0[u + 1];
      float w1a = sw0[256 + u], w1b = sw0[257 + u];
      float w2a = sw0[512 + u], w2b = sw0[513 + u];
      float ca = sc0[u], cb = sc0[u + 1];
      #pragma unroll
      for (int pi = 0; pi < 2; pi++) {
        float ha = fmaxf(ca + xv[pi][0] * w0a + xv[pi][1] * w1a + xv[pi][2] * w2a, 0.f);
        float hb = fmaxf(cb + xv[pi][0] * w0b + xv[pi][1] * w1b + xv[pi][2] * w2b, 0.f);
        a[half8 * 2 + pi] = packh2(ha, hb);
      }
    }
    sA[(wid * 16 + kb) * 32 + lane] = make_uint4(a[0], a[1], a[2], a[3]);
  }
  __syncthreads();

  // ---- 3 hidden layers: warp tile 64x64 (wn=wid); B via LDG; A double-buffered ----
  float acc[4][8][4];

  #pragma unroll 1
  for (int l = 0; l < 3; l++) {
    const uint4* Ard = sA + (l & 1) * 2048;
    uint4* Awr = sA + ((l + 1) & 1) * 2048;

    // bias for this warp's 64 columns; init accumulators with it
    const float* bias = sb + l * 256;
    float bv[4][4];
    #pragma unroll
    for (int jj = 0; jj < 4; jj++) {
      int c = wid * 64 + jj * 16 + tg * 2;
      bv[jj][0] = bias[c];     bv[jj][1] = bias[c + 1];
      bv[jj][2] = bias[c + 8]; bv[jj][3] = bias[c + 9];
    }
    #pragma unroll
    for (int i = 0; i < 4; i++)
      #pragma unroll
      for (int jj = 0; jj < 4; jj++) {
        acc[i][2 * jj][0] = bv[jj][0]; acc[i][2 * jj][1] = bv[jj][1];
        acc[i][2 * jj][2] = bv[jj][0]; acc[i][2 * jj][3] = bv[jj][1];
        acc[i][2 * jj + 1][0] = bv[jj][2]; acc[i][2 * jj + 1][1] = bv[jj][3];
        acc[i][2 * jj + 1][2] = bv[jj][2]; acc[i][2 * jj + 1][3] = bv[jj][3];
      }

    const uint4* gB = (const uint4*)g_bf[l];
    uint4 bf[3][4];
    #pragma unroll
    for (int j = 0; j < 4; j++) {
      bf[0][j] = __ldg(gB + (0 * 16 + wid * 4 + j) * 32 + lane);
      bf[1][j] = __ldg(gB + (1 * 16 + wid * 4 + j) * 32 + lane);
    }

    #pragma unroll
    for (int kb = 0; kb < 16; kb++) {
      int cur = kb % 3;
      if (kb < 14) {
        int nxt = (kb + 2) % 3;
        #pragma unroll
        for (int j = 0; j < 4; j++)
          bf[nxt][j] = __ldg(gB + ((kb + 2) * 16 + wid * 4 + j) * 32 + lane);
      }
      uint4 af[4];
      #pragma unroll
      for (int i = 0; i < 4; i++) af[i] = Ard[(i * 16 + kb) * 32 + lane];
      #pragma unroll
      for (int i = 0; i < 4; i++)
        #pragma unroll
        for (int j = 0; j < 4; j++) {
          mma16816(acc[i][2 * j],     af[i], bf[cur][j].x, bf[cur][j].y);
          mma16816(acc[i][2 * j + 1], af[i], bf[cur][j].z, bf[cur][j].w);
        }
    }

    // epilogue: tanh on packed f16x2 (bias already in acc); write OTHER buffer
    #pragma unroll
    for (int jj = 0; jj < 4; jj++) {
      #pragma unroll
      for (int i = 0; i < 4; i++) {
        float* e = acc[i][2 * jj];
        float* o = acc[i][2 * jj + 1];
        uint32_t a0 = tanh2(packh2(e[0], e[1]));
        uint32_t a1 = tanh2(packh2(e[2], e[3]));
        uint32_t a2 = tanh2(packh2(o[0], o[1]));
        uint32_t a3 = tanh2(packh2(o[2], o[3]));
        Awr[(i * 16 + (wid * 4 + jj)) * 32 + lane] = make_uint4(a0, a1, a2, a3);
      }
    }
    __syncthreads();   // epilogue writes visible before next layer's MMA reads
  }

  // ---- final: res = z @ W4 + b4; out = clip(x + res); z in sA buffer 1 ----
  const uint4* Afin = sA + 2048;
  float r0[3] = {0.f, 0.f, 0.f}, r1[3] = {0.f, 0.f, 0.f};
  #pragma unroll 4
  for (int kb = 0; kb < 16; kb++) {
    uint4 a = Afin[(wid * 16 + kb) * 32 + lane];
    int k0 = kb * 16 + tg * 2;
    uint32_t regs[4] = {a.x, a.y, a.z, a.w};
    #pragma unroll
    for (int half8 = 0; half8 < 2; half8++) {
      int u = k0 + half8 * 8;
      float w_a[3], w_b[3];
      #pragma unroll
      for (int c = 0; c < 3; c++) { w_a[c] = sw4[u * 3 + c]; w_b[c] = sw4[(u + 1) * 3 + c]; }
      #pragma unroll
      for (int pi = 0; pi < 2; pi++) {
        __half2 h = *(__half2*)&regs[half8 * 2 + pi];
        float za = __half2float(__low2half(h)), zb = __half2float(__high2half(h));
        float* r = pi ? r1 : r0;
        #pragma unroll
        for (int c = 0; c < 3; c++) r[c] += za * w_a[c] + zb * w_b[c];
      }
    }
  }
  #pragma unroll
  for (int c = 0; c < 3; c++) {
    r0[c] += __shfl_xor_sync(0xFFFFFFFF, r0[c], 1);
    r0[c] += __shfl_xor_sync(0xFFFFFFFF, r0[c], 2);
    r1[c] += __shfl_xor_sync(0xFFFFFFFF, r1[c], 1);
    r1[c] += __shfl_xor_sync(0xFFFFFFFF, r1[c], 2);
  }
  if (tg < 3) {
    float o0 = fminf(fmaxf(xv[0][tg] + r0[tg] + sb4[tg], 0.f), 1.f);
    float o1 = fminf(fmaxf(xv[1][tg] + r1[tg] + sb4[tg], 0.f), 1.f);
    float* ob = out + (size_t)img * 3 * HW_ + (size_t)tg * HW_ + hw;
    ob[0] = o0; ob[8] = o1;
  }
}

extern "C" void kernel_launch(void* const* d_in, const int* in_sizes, int n_in,
                              void* d_out, int out_size) {
  const float* x     = (const float*)d_in[0];
  const float* style = (const float*)d_in[1];
  const float* W0    = (const float*)d_in[2];
  const float* b0    = (const float*)d_in[3];
  const float* W1    = (const float*)d_in[4];
  const float* b1    = (const float*)d_in[5];
  const float* W2    = (const float*)d_in[6];
  const float* b2    = (const float*)d_in[7];
  const float* W3    = (const float*)d_in[8];
  const float* b3    = (const float*)d_in[9];
  const float* W4    = (const float*)d_in[10];
  const float* b4    = (const float*)d_in[11];
  float* out = (float*)d_out;

  prep_kernel<<<768, 256>>>(W1, W2, W3);
  cudaFuncSetAttribute(cnilut_main, cudaFuncAttributeMaxDynamicSharedMemorySize, SMEM_TOTAL);
  cnilut_main<<<GRID, 128, SMEM_TOTAL>>>(x, style, W0, b0, b1, b2, b3, W4, b4, out);
}

// round 5
// speedup vs baseline: 1.5704x; 1.0259x over previous
#include <cuda_runtime.h>
#include <cuda_fp16.h>
#include <cstdint>

#define HW_ 262144            // 512*512
#define TILE 64
#define GRID 16384

// Fragment-linear fp16 weight images for mma.sync m16n8k16 B operand.
__device__ __align__(16) __half g_bf[3][65536];  // W1..W3 [kb(16)][n8pair(16)][lane(32)][8]
__device__ __align__(16) __half g_w0f[4096];     // W0 [1 kb][n8pair(16)][lane(32)][8], k<3 live
__device__ __align__(16) __half g_w4f[2048];     // W4 [kb(16)][lane(32)][b0,b1 halves]

// ---------------- prep: fp32 W -> fp16 fragment-linear ----------------
__global__ void prep_kernel(const float* __restrict__ W0, const float* __restrict__ W1,
                            const float* __restrict__ W2, const float* __restrict__ W3,
                            const float* __restrict__ W4) {
  int t = blockIdx.x * blockDim.x + threadIdx.x;   // 202752 threads
  if (t < 196608) {
    int l = t >> 16, e = t & 65535;
    int k = e >> 8, n = e & 255;
    const float* W = (l == 0) ? W1 : (l == 1 ? W2 : W3);
    int kb = k >> 4, kr = k & 15;
    int n8 = n >> 3, g = n & 7;
    int tg = (kr >> 1) & 3;
    int lane = g * 4 + tg;
    int breg = kr >> 3, hs = kr & 1;
    int halfidx = (n8 & 1) * 4 + breg * 2 + hs;
    int dst = ((kb * 16 + (n8 >> 1)) * 32 + lane) * 8 + halfidx;
    g_bf[l][dst] = __float2half_rn(W[k * 256 + n]);
  } else if (t < 200704) {
    int e = t - 196608;                  // k(16) x n(256)
    int k = e >> 8, n = e & 255;
    int n8 = n >> 3, g = n & 7;
    int tg = (k >> 1) & 3;
    int lane = g * 4 + tg;
    int breg = k >> 3, hs = k & 1;
    int halfidx = (n8 & 1) * 4 + breg * 2 + hs;
    int dst = ((n8 >> 1) * 32 + lane) * 8 + halfidx;
    g_w0f[dst] = __float2half_rn(k < 3 ? W0[k * 256 + n] : 0.f);
  } else if (t < 202752) {
    int e = t - 200704;                  // kglob(256) x n(8)
    int kglob = e >> 3, n = e & 7;
    int kbG = kglob >> 4, kr = kglob & 15;
    int tg = (kr >> 1) & 3;
    int lane = n * 4 + tg;
    int breg = kr >> 3, hs = kr & 1;
    int dst = ((kbG * 32 + lane) * 2 + breg) * 2 + hs;
    g_w4f[dst] = __float2half_rn(n < 3 ? W4[kglob * 3 + n] : 0.f);
  }
}

// ---------------- helpers ----------------
__device__ __forceinline__ uint32_t packh2(float lo, float hi) {
  uint32_t r;
  asm("cvt.rn.f16x2.f32 %0, %1, %2;" : "=f"(*(float*)&r) : "f"(hi), "f"(lo));
  return r;
}
__device__ __forceinline__ uint32_t tanh2(uint32_t p) {
  uint32_t r;
  asm("tanh.approx.f16x2 %0, %1;" : "=r"(r) : "r"(p));
  return r;
}
__device__ __forceinline__ uint32_t max0h2(uint32_t p) {
  uint32_t r;
  asm("max.f16x2 %0, %1, %2;" : "=r"(r) : "r"(p), "r"(0u));
  return r;
}
__device__ __forceinline__ void mma16816(float* c, const uint4& a, uint32_t b0, uint32_t b1) {
  asm volatile("mma.sync.aligned.m16n8k16.row.col.f32.f16.f16.f32 "
               "{%0,%1,%2,%3}, {%4,%5,%6,%7}, {%8,%9}, {%0,%1,%2,%3};"
               : "+f"(c[0]), "+f"(c[1]), "+f"(c[2]), "+f"(c[3])
               : "r"(a.x), "r"(a.y), "r"(a.z), "r"(a.w), "r"(b0), "r"(b1));
}

// ---------------- SMEM layout (dynamic) ----------------
// [0:65536)       sA double-buffered: 2 x 2048 uint4 (buf1 reused as final-partial scratch)
// [65536:66560)   sc0 (256 f)
// [66560:69632)   sb  (768 f)
// [69632:69648)   sb4 (4 f)
#define SMEM_TOTAL 69648

__global__ void __launch_bounds__(128, 2) cnilut_main(
    const float* __restrict__ x, const float* __restrict__ style,
    const float* __restrict__ W0, const float* __restrict__ b0,
    const float* __restrict__ b1, const float* __restrict__ b2,
    const float* __restrict__ b3, const float* __restrict__ b4,
    float* __restrict__ out) {
  extern __shared__ char smem[];
  uint4* sA  = (uint4*)smem;
  float* sc0 = (float*)(smem + 65536);
  float* sb  = (float*)(smem + 66560);
  float* sb4 = (float*)(smem + 69632);

  int tid = threadIdx.x, wid = tid >> 5, lane = tid & 31;
  int g = lane >> 2, tg = lane & 3;

  // ---- early LDGs: layer0 B fragments + own pixels ----
  uint4 bf0[4];
  #pragma unroll
  for (int j = 0; j < 4; j++)
    bf0[j] = __ldg((const uint4*)g_w0f + (wid * 4 + j) * 32 + lane);

  int p0 = blockIdx.x * TILE + wid * 16 + g;
  int img = p0 >> 18, hw = p0 & (HW_ - 1);
  const float* xb = x + (size_t)img * 3 * HW_ + hw;
  float xv[2][3];
  #pragma unroll
  for (int c = 0; c < 3; c++) { xv[0][c] = xb[(size_t)c * HW_]; xv[1][c] = xb[(size_t)c * HW_ + 8]; }

  // layer0 A fragments from x (k = tg*2, tg*2+1; only k<3 live)
  uint4 af0[4];
  #pragma unroll
  for (int i = 0; i < 4; i++) {
    uint32_t ax = 0, ay = 0;
    if (tg < 2) {
      int rp = blockIdx.x * TILE + i * 16 + g;
      int im2 = rp >> 18, hw2 = rp & (HW_ - 1);
      const float* xq = x + (size_t)im2 * 3 * HW_ + hw2;
      float va  = (tg == 0) ? xq[0]        : xq[2 * (size_t)HW_];
      float vb  = (tg == 0) ? xq[HW_]      : 0.f;
      float va2 = (tg == 0) ? xq[8]        : xq[2 * (size_t)HW_ + 8];
      float vb2 = (tg == 0) ? xq[HW_ + 8]  : 0.f;
      ax = packh2(va, vb);
      ay = packh2(va2, vb2);
    }
    af0[i] = make_uint4(ax, ay, 0u, 0u);
  }

  // per-CTA params
  {
    float s0 = style[0], s1 = style[1], s2 = style[2];
    #pragma unroll
    for (int i = 0; i < 6; i++) {
      int u = tid + i * 128;
      sb[u] = (u < 256) ? b1[u] : (u < 512 ? b2[u - 256] : b3[u - 512]);
    }
    #pragma unroll
    for (int i = 0; i < 2; i++) {
      int u = tid + i * 128;
      sc0[u] = b0[u] + s0 * W0[768 + u] + s1 * W0[1024 + u] + s2 * W0[1280 + u];
    }
    if (tid < 3) sb4[tid] = b4[tid];
  }
  __syncthreads();

  float acc[4][8][4];

  // ---- layer 0 via MMA: relu(x.W0 + c0) -> sA buf0 ----
  {
    #pragma unroll
    for (int jj = 0; jj < 4; jj++) {
      int c = wid * 64 + jj * 16 + tg * 2;
      float bv0 = sc0[c], bv1 = sc0[c + 1], bv8 = sc0[c + 8], bv9 = sc0[c + 9];
      #pragma unroll
      for (int i = 0; i < 4; i++) {
        acc[i][2 * jj][0] = bv0; acc[i][2 * jj][1] = bv1;
        acc[i][2 * jj][2] = bv0; acc[i][2 * jj][3] = bv1;
        acc[i][2 * jj + 1][0] = bv8; acc[i][2 * jj + 1][1] = bv9;
        acc[i][2 * jj + 1][2] = bv8; acc[i][2 * jj + 1][3] = bv9;
      }
    }
    #pragma unroll
    for (int i = 0; i < 4; i++)
      #pragma unroll
      for (int j = 0; j < 4; j++) {
        mma16816(acc[i][2 * j],     af0[i], bf0[j].x, bf0[j].y);
        mma16816(acc[i][2 * j + 1], af0[i], bf0[j].z, bf0[j].w);
      }
  }

  // prefetch first B fragments of hidden layer 0 (hides LDG latency behind epilogue)
  uint4 bfp0[4], bfp1[4];
  {
    const uint4* gB = (const uint4*)g_bf[0];
    #pragma unroll
    for (int j = 0; j < 4; j++) {
      bfp0[j] = __ldg(gB + (0 * 16 + wid * 4 + j) * 32 + lane);
      bfp1[j] = __ldg(gB + (1 * 16 + wid * 4 + j) * 32 + lane);
    }
  }

  // layer0 epilogue: relu + pack -> buf0
  #pragma unroll
  for (int jj = 0; jj < 4; jj++) {
    #pragma unroll
    for (int i = 0; i < 4; i++) {
      float* e = acc[i][2 * jj];
      float* o = acc[i][2 * jj + 1];
      uint32_t a0 = max0h2(packh2(e[0], e[1]));
      uint32_t a1 = max0h2(packh2(e[2], e[3]));
      uint32_t a2 = max0h2(packh2(o[0], o[1]));
      uint32_t a3 = max0h2(packh2(o[2], o[3]));
      sA[(i * 16 + (wid * 4 + jj)) * 32 + lane] = make_uint4(a0, a1, a2, a3);
    }
  }
  __syncthreads();

  // ---- 3 hidden layers ----
  float res[4][4];
  uint2 wb[4];

  #pragma unroll 1
  for (int l = 0; l < 3; l++) {
    const uint4* Ard = sA + (l & 1) * 2048;
    uint4* Awr = sA + ((l + 1) & 1) * 2048;

    const float* bias = sb + l * 256;
    #pragma unroll
    for (int jj = 0; jj < 4; jj++) {
      int c = wid * 64 + jj * 16 + tg * 2;
      float bv0 = bias[c], bv1 = bias[c + 1], bv8 = bias[c + 8], bv9 = bias[c + 9];
      #pragma unroll
      for (int i = 0; i < 4; i++) {
        acc[i][2 * jj][0] = bv0; acc[i][2 * jj][1] = bv1;
        acc[i][2 * jj][2] = bv0; acc[i][2 * jj][3] = bv1;
        acc[i][2 * jj + 1][0] = bv8; acc[i][2 * jj + 1][1] = bv9;
        acc[i][2 * jj + 1][2] = bv8; acc[i][2 * jj + 1][3] = bv9;
      }
    }

    const uint4* gB = (const uint4*)g_bf[l];
    uint4 bf[3][4];
    #pragma unroll
    for (int j = 0; j < 4; j++) { bf[0][j] = bfp0[j]; bf[1][j] = bfp1[j]; }

    #pragma unroll
    for (int kb = 0; kb < 16; kb++) {
      int cur = kb % 3;
      if (kb < 14) {
        int nxt = (kb + 2) % 3;
        #pragma unroll
        for (int j = 0; j < 4; j++)
          bf[nxt][j] = __ldg(gB + ((kb + 2) * 16 + wid * 4 + j) * 32 + lane);
      }
      uint4 af[4];
      #pragma unroll
      for (int i = 0; i < 4; i++) af[i] = Ard[(i * 16 + kb) * 32 + lane];
      #pragma unroll
      for (int i = 0; i < 4; i++)
        #pragma unroll
        for (int j = 0; j < 4; j++) {
          mma16816(acc[i][2 * j],     af[i], bf[cur][j].x, bf[cur][j].y);
          mma16816(acc[i][2 * j + 1], af[i], bf[cur][j].z, bf[cur][j].w);
        }
    }

    if (l < 2) {
      // prefetch next layer's first B fragments before epilogue
      const uint4* gBn = (const uint4*)g_bf[l + 1];
      #pragma unroll
      for (int j = 0; j < 4; j++) {
        bfp0[j] = __ldg(gBn + (0 * 16 + wid * 4 + j) * 32 + lane);
        bfp1[j] = __ldg(gBn + (1 * 16 + wid * 4 + j) * 32 + lane);
      }
      // epilogue: tanh + pack -> other buffer
      #pragma unroll
      for (int jj = 0; jj < 4; jj++) {
        #pragma unroll
        for (int i = 0; i < 4; i++) {
          float* e = acc[i][2 * jj];
          float* o = acc[i][2 * jj + 1];
          uint32_t a0 = tanh2(packh2(e[0], e[1]));
          uint32_t a1 = tanh2(packh2(e[2], e[3]));
          uint32_t a2 = tanh2(packh2(o[0], o[1]));
          uint32_t a3 = tanh2(packh2(o[2], o[3]));
          Awr[(i * 16 + (wid * 4 + jj)) * 32 + lane] = make_uint4(a0, a1, a2, a3);
        }
      }
    } else {
      // final layer fused into epilogue: tanh-pack -> 16 HMMA (own k-slice) -> partials
      #pragma unroll
      for (int jj = 0; jj < 4; jj++)
        wb[jj] = __ldg((const uint2*)g_w4f + (wid * 4 + jj) * 32 + lane);
      #pragma unroll
      for (int i = 0; i < 4; i++)
        #pragma unroll
        for (int r = 0; r < 4; r++) res[i][r] = 0.f;
      #pragma unroll
      for (int jj = 0; jj < 4; jj++) {
        #pragma unroll
        for (int i = 0; i < 4; i++) {
          float* e = acc[i][2 * jj];
          float* o = acc[i][2 * jj + 1];
          uint4 frag;
          frag.x = tanh2(packh2(e[0], e[1]));
          frag.y = tanh2(packh2(e[2], e[3]));
          frag.z = tanh2(packh2(o[0], o[1]));
          frag.w = tanh2(packh2(o[2], o[3]));
          mma16816(res[i], frag, wb[jj].x, wb[jj].y);
        }
      }
      // store partials into buf1 (free: last read ended at l==1's barrier)
      float4* P = (float4*)(sA + 2048);
      #pragma unroll
      for (int i = 0; i < 4; i++)
        P[(wid * 4 + i) * 32 + lane] = make_float4(res[i][0], res[i][1], res[i][2], res[i][3]);
    }
    __syncthreads();
  }

  // ---- cross-warp reduce + residual + clip + store ----
  {
    const float4* P = (const float4*)(sA + 2048);
    float4 q0 = P[(0 * 4 + wid) * 32 + lane];
    float4 q1 = P[(1 * 4 + wid) * 32 + lane];
    float4 q2 = P[(2 * 4 + wid) * 32 + lane];
    float4 q3 = P[(3 * 4 + wid) * 32 + lane];
    float r0 = q0.x + q1.x + q2.x + q3.x;   // pixel row g,   col tg*2
    float r1 = q0.y + q1.y + q2.y + q3.y;   // pixel row g,   col tg*2+1
    float r2 = q0.z + q1.z + q2.z + q3.z;   // pixel row g+8, col tg*2
    float r3 = q0.w + q1.w + q2.w + q3.w;   // pixel row g+8, col tg*2+1
    float* ob = out + (size_t)img * 3 * HW_ + hw;
    if (tg == 0) {
      ob[0]        = fminf(fmaxf(xv[0][0] + r0 + sb4[0], 0.f), 1.f);
      ob[HW_]      = fminf(fmaxf(xv[0][1] + r1 + sb4[1], 0.f), 1.f);
      ob[8]        = fminf(fmaxf(xv[1][0] + r2 + sb4[0], 0.f), 1.f);
      ob[HW_ + 8]  = fminf(fmaxf(xv[1][1] + r3 + sb4[1], 0.f), 1.f);
    } else if (tg == 1) {
      ob[2 * (size_t)HW_]     = fminf(fmaxf(xv[0][2] + r0 + sb4[2], 0.f), 1.f);
      ob[2 * (size_t)HW_ + 8] = fminf(fmaxf(xv[1][2] + r2 + sb4[2], 0.f), 1.f);
    }
  }
}

extern "C" void kernel_launch(void* const* d_in, const int* in_sizes, int n_in,
                              void* d_out, int out_size) {
  const float* x     = (const float*)d_in[0];
  const float* style = (const float*)d_in[1];
  const float* W0    = (const float*)d_in[2];
  const float* b0    = (const float*)d_in[3];
  const float* W1    = (const float*)d_in[4];
  const float* b1    = (const float*)d_in[5];
  const float* W2    = (const float*)d_in[6];
  const float* b2    = (const float*)d_in[7];
  const float* W3    = (const float*)d_in[8];
  const float* b3    = (const float*)d_in[9];
  const float* W4    = (const float*)d_in[10];
  const float* b4    = (const float*)d_in[11];
  float* out = (float*)d_out;

  prep_kernel<<<792, 256>>>(W0, W1, W2, W3, W4);
  cudaFuncSetAttribute(cnilut_main, cudaFuncAttributeMaxDynamicSharedMemorySize, SMEM_TOTAL);
  cnilut_main<<<GRID, 128, SMEM_TOTAL>>>(x, style, W0, b0, b1, b2, b3, b4, out);
}